// round 1
// baseline (speedup 1.0000x reference)
#include <cuda_runtime.h>
#include <math.h>

// Problem constants (fixed shapes for this problem instance)
#define S_LEN 2048
#define B_SZ  64
#define H_DIM 1024
#define D_HALF 64
#define W_WIN 129          // 2*D+1
#define DCH   64           // d-chunk for GEMM partial
#define NDC   (H_DIM / DCH)  // 16 d-chunks

// Scratch (allocation-free: __device__ globals)
__device__ float g_dotp[NDC * B_SZ * H_DIM];   // [dc][b][h]  4 MB
__device__ float g_p[B_SZ];
__device__ int   g_center[B_SZ];
__device__ float g_scores[B_SZ * W_WIN];
__device__ float g_attn[B_SZ * W_WIN];

// ---------------------------------------------------------------------------
// K1: partial GEMM  dotp[dc][b][h] = sum_{d in chunk dc} hidden[b][d]*Wp_w[h][d]
// grid: (16 h-tiles, 16 d-chunks), 256 threads.
// Block tile: 64 b x 64 h over a 64-wide d chunk. Thread tile: 4b x 4h.
// ---------------------------------------------------------------------------
__global__ __launch_bounds__(256, 2)
void k_gemm_partial(const float* __restrict__ hidden,
                    const float* __restrict__ Wp_w) {
    const int h0 = blockIdx.x * 64;
    const int dc = blockIdx.y;
    const int d0 = dc * DCH;

    __shared__ float sh_h[64][65];   // [b][d] padded
    __shared__ float sh_w[DCH][65];  // [d][h] padded (transposed)

    const int tid  = threadIdx.x;
    const int lane = tid & 31;
    const int warp = tid >> 5;

    // load hidden chunk [64b x 64d]
    for (int idx = tid; idx < 64 * 16; idx += 256) {
        int b  = idx >> 4;
        int dq = (idx & 15) << 2;
        float4 v = *reinterpret_cast<const float4*>(&hidden[b * H_DIM + d0 + dq]);
        sh_h[b][dq + 0] = v.x; sh_h[b][dq + 1] = v.y;
        sh_h[b][dq + 2] = v.z; sh_h[b][dq + 3] = v.w;
    }
    // load Wp chunk [64h x 64d], store transposed [d][h]
    for (int idx = tid; idx < 64 * 16; idx += 256) {
        int h  = idx >> 4;
        int dq = (idx & 15) << 2;
        float4 v = *reinterpret_cast<const float4*>(&Wp_w[(size_t)(h0 + h) * H_DIM + d0 + dq]);
        sh_w[dq + 0][h] = v.x; sh_w[dq + 1][h] = v.y;
        sh_w[dq + 2][h] = v.z; sh_w[dq + 3][h] = v.w;
    }
    __syncthreads();

    const int hl = lane & 15;                       // 0..15
    const int bl = ((lane >> 4) << 2) + (warp << 3); // {0,4}+8*warp

    float acc[4][4] = {};
#pragma unroll 16
    for (int d = 0; d < DCH; ++d) {
        float wv0 = sh_w[d][hl];
        float wv1 = sh_w[d][hl + 16];
        float wv2 = sh_w[d][hl + 32];
        float wv3 = sh_w[d][hl + 48];
        float hv0 = sh_h[bl + 0][d];
        float hv1 = sh_h[bl + 1][d];
        float hv2 = sh_h[bl + 2][d];
        float hv3 = sh_h[bl + 3][d];
        acc[0][0] += hv0 * wv0; acc[0][1] += hv0 * wv1; acc[0][2] += hv0 * wv2; acc[0][3] += hv0 * wv3;
        acc[1][0] += hv1 * wv0; acc[1][1] += hv1 * wv1; acc[1][2] += hv1 * wv2; acc[1][3] += hv1 * wv3;
        acc[2][0] += hv2 * wv0; acc[2][1] += hv2 * wv1; acc[2][2] += hv2 * wv2; acc[2][3] += hv2 * wv3;
        acc[3][0] += hv3 * wv0; acc[3][1] += hv3 * wv1; acc[3][2] += hv3 * wv2; acc[3][3] += hv3 * wv3;
    }

    float* outp = &g_dotp[(size_t)dc * (B_SZ * H_DIM)];
#pragma unroll
    for (int j = 0; j < 4; ++j) {
        int b = bl + j;
#pragma unroll
        for (int i = 0; i < 4; ++i) {
            int h = h0 + hl + 16 * i;
            outp[b * H_DIM + h] = acc[j][i];
        }
    }
}

// ---------------------------------------------------------------------------
// K2: per-b reduce -> p[b], center[b]
// grid: 64 blocks (one per b), 256 threads
// ---------------------------------------------------------------------------
__global__ __launch_bounds__(256)
void k_reduce_p(const float* __restrict__ Wp_b,
                const float* __restrict__ vp_w,
                const float* __restrict__ vp_b) {
    const int b = blockIdx.x;
    const int tid = threadIdx.x;
    float local = 0.f;
    for (int h = tid; h < H_DIM; h += 256) {
        float s = Wp_b[h];
#pragma unroll
        for (int dc = 0; dc < NDC; ++dc)
            s += g_dotp[(size_t)dc * (B_SZ * H_DIM) + b * H_DIM + h];
        local += vp_w[h] * tanhf(s);
    }
    __shared__ float red[256];
    red[tid] = local;
    __syncthreads();
    for (int s = 128; s > 0; s >>= 1) {
        if (tid < s) red[tid] += red[tid + s];
        __syncthreads();
    }
    if (tid == 0) {
        float tot = red[0] + vp_b[0];
        float p = (float)S_LEN / (1.f + expf(-tot));
        g_p[b] = p;
        g_center[b] = (int)rintf(p);   // round-half-even, matches jnp.round
    }
}

// ---------------------------------------------------------------------------
// K3: scores[b][w] = dot(hidden[b,:], enc[s,b,:]),  s = center[b]+w-D
//     out-of-range s -> exact 0.0 (padded zero rows in reference)
// grid: (17 w-groups of 8, 64 b), 256 threads (one warp per w)
// ---------------------------------------------------------------------------
__global__ __launch_bounds__(256)
void k_scores(const float* __restrict__ hidden,
              const float* __restrict__ enc) {
    const int b = blockIdx.y;
    __shared__ __align__(16) float sh_hid[H_DIM];
    const int tid = threadIdx.x;
    for (int i = tid; i < H_DIM; i += 256) sh_hid[i] = hidden[b * H_DIM + i];
    __syncthreads();

    const int w = blockIdx.x * 8 + (tid >> 5);
    const int lane = tid & 31;
    if (w >= W_WIN) return;

    const int s = g_center[b] + w - D_HALF;
    float score = 0.f;
    if (s >= 0 && s < S_LEN) {
        const float4* e4 = reinterpret_cast<const float4*>(enc + ((size_t)s * B_SZ + b) * H_DIM);
        const float4* h4 = reinterpret_cast<const float4*>(sh_hid);
        float a0 = 0.f, a1 = 0.f, a2 = 0.f, a3 = 0.f;
#pragma unroll
        for (int k = 0; k < 8; ++k) {
            float4 e = e4[k * 32 + lane];
            float4 hh = h4[k * 32 + lane];
            a0 += e.x * hh.x; a1 += e.y * hh.y;
            a2 += e.z * hh.z; a3 += e.w * hh.w;
        }
        float v = (a0 + a1) + (a2 + a3);
#pragma unroll
        for (int off = 16; off > 0; off >>= 1)
            v += __shfl_down_sync(0xffffffffu, v, off);
        score = v;
    }
    if (lane == 0) g_scores[b * W_WIN + w] = score;
}

// ---------------------------------------------------------------------------
// K4: softmax over w + gaussian scaling; writes attn_scaled to d_out[0:B*W]
// grid: 64 blocks, 256 threads
// ---------------------------------------------------------------------------
__global__ __launch_bounds__(256)
void k_softmax(float* __restrict__ d_out) {
    const int b = blockIdx.x;
    const int tid = threadIdx.x;
    __shared__ float red[256];

    float sc = (tid < W_WIN) ? g_scores[b * W_WIN + tid] : -1e30f;
    red[tid] = sc;
    __syncthreads();
    for (int s = 128; s > 0; s >>= 1) {
        if (tid < s) red[tid] = fmaxf(red[tid], red[tid + s]);
        __syncthreads();
    }
    float mx = red[0];
    __syncthreads();

    float e = (tid < W_WIN) ? expf(sc - mx) : 0.f;
    red[tid] = e;
    __syncthreads();
    for (int s = 128; s > 0; s >>= 1) {
        if (tid < s) red[tid] += red[tid + s];
        __syncthreads();
    }
    float denom = red[0];

    if (tid < W_WIN) {
        float p = g_p[b];
        float pos = (float)(g_center[b] + tid - D_HALF);
        float diff = pos - p;
        float val = (e / denom) * expf(-diff * diff * (1.f / 2048.f)); // stddev=D/2=32
        d_out[b * W_WIN + tid] = val;
        g_attn[b * W_WIN + tid] = val;
    }
}

// ---------------------------------------------------------------------------
// K5: context[b][h] = sum_w attn[b][w] * enc[s,b,h]
// grid: (4 h-quarters, 64 b), 64 threads; thread owns one float4 of h
// ---------------------------------------------------------------------------
__global__ __launch_bounds__(64)
void k_context(const float* __restrict__ enc,
               float* __restrict__ d_out) {
    const int hq = blockIdx.x;
    const int b  = blockIdx.y;
    const int tid = threadIdx.x;

    __shared__ float sa[W_WIN];
    for (int i = tid; i < W_WIN; i += 64) sa[i] = g_attn[b * W_WIN + i];
    __syncthreads();

    const int c = g_center[b];
    const int wlo = max(0, D_HALF - c);
    const int whi = min(W_WIN, S_LEN + D_HALF - c);  // s < S_LEN
    const int h = hq * 256 + tid * 4;

    const float* base = enc + (size_t)b * H_DIM + h;
    float4 acc = make_float4(0.f, 0.f, 0.f, 0.f);
#pragma unroll 8
    for (int w = wlo; w < whi; ++w) {
        int s = c + w - D_HALF;
        float4 e = *reinterpret_cast<const float4*>(base + (size_t)s * (B_SZ * H_DIM));
        float a = sa[w];
        acc.x += a * e.x; acc.y += a * e.y;
        acc.z += a * e.z; acc.w += a * e.w;
    }
    *reinterpret_cast<float4*>(d_out + B_SZ * W_WIN + b * H_DIM + h) = acc;
}

// ---------------------------------------------------------------------------
extern "C" void kernel_launch(void* const* d_in, const int* in_sizes, int n_in,
                              void* d_out, int out_size) {
    // metadata order: t, hidden, encoder_outputs, Wp_w, Wp_b, vp_w, vp_b
    const float* hidden = (const float*)d_in[1];
    const float* enc    = (const float*)d_in[2];
    const float* Wp_w   = (const float*)d_in[3];
    const float* Wp_b   = (const float*)d_in[4];
    const float* vp_w   = (const float*)d_in[5];
    const float* vp_b   = (const float*)d_in[6];
    float* out = (float*)d_out;

    k_gemm_partial<<<dim3(16, 16), 256>>>(hidden, Wp_w);
    k_reduce_p<<<64, 256>>>(Wp_b, vp_w, vp_b);
    k_scores<<<dim3(17, 64), 256>>>(hidden, enc);
    k_softmax<<<64, 256>>>(out);
    k_context<<<dim3(4, 64), 64>>>(enc, out);
}

// round 2
// speedup vs baseline: 1.0077x; 1.0077x over previous
#include <cuda_runtime.h>
#include <math.h>

// Problem constants (fixed shapes)
#define S_LEN 2048
#define B_SZ  64
#define H_DIM 1024
#define D_HALF 64
#define W_WIN 129          // 2*D+1
#define DCH   64           // d-chunk for GEMM partial
#define NDC   (H_DIM / DCH)  // 16

// Scratch (allocation-free)
__device__ float g_dotp[NDC * B_SZ * H_DIM];   // [dc][b][h]  4 MB

// ---------------------------------------------------------------------------
// K1: partial GEMM  dotp[dc][b][h] = sum_{d in chunk dc} hidden[b][d]*Wp_w[h][d]
// grid: (16 h-tiles, 16 d-chunks), 256 threads. Thread tile 4b x 4h.
// fp32 on purpose: p feeds round() -> window center; precision is structural.
// ---------------------------------------------------------------------------
__global__ __launch_bounds__(256, 2)
void k_gemm_partial(const float* __restrict__ hidden,
                    const float* __restrict__ Wp_w) {
    const int h0 = blockIdx.x * 64;
    const int dc = blockIdx.y;
    const int d0 = dc * DCH;

    __shared__ float sh_h[64][65];   // [b][d] padded
    __shared__ float sh_w[DCH][65];  // [d][h] padded (transposed)

    const int tid  = threadIdx.x;
    const int lane = tid & 31;
    const int warp = tid >> 5;

    for (int idx = tid; idx < 64 * 16; idx += 256) {
        int b  = idx >> 4;
        int dq = (idx & 15) << 2;
        float4 v = *reinterpret_cast<const float4*>(&hidden[b * H_DIM + d0 + dq]);
        sh_h[b][dq + 0] = v.x; sh_h[b][dq + 1] = v.y;
        sh_h[b][dq + 2] = v.z; sh_h[b][dq + 3] = v.w;
    }
    for (int idx = tid; idx < 64 * 16; idx += 256) {
        int h  = idx >> 4;
        int dq = (idx & 15) << 2;
        float4 v = *reinterpret_cast<const float4*>(&Wp_w[(size_t)(h0 + h) * H_DIM + d0 + dq]);
        sh_w[dq + 0][h] = v.x; sh_w[dq + 1][h] = v.y;
        sh_w[dq + 2][h] = v.z; sh_w[dq + 3][h] = v.w;
    }
    __syncthreads();

    const int hl = lane & 15;
    const int bl = ((lane >> 4) << 2) + (warp << 3);

    float acc[4][4] = {};
#pragma unroll 16
    for (int d = 0; d < DCH; ++d) {
        float wv0 = sh_w[d][hl];
        float wv1 = sh_w[d][hl + 16];
        float wv2 = sh_w[d][hl + 32];
        float wv3 = sh_w[d][hl + 48];
        float hv0 = sh_h[bl + 0][d];
        float hv1 = sh_h[bl + 1][d];
        float hv2 = sh_h[bl + 2][d];
        float hv3 = sh_h[bl + 3][d];
        acc[0][0] += hv0 * wv0; acc[0][1] += hv0 * wv1; acc[0][2] += hv0 * wv2; acc[0][3] += hv0 * wv3;
        acc[1][0] += hv1 * wv0; acc[1][1] += hv1 * wv1; acc[1][2] += hv1 * wv2; acc[1][3] += hv1 * wv3;
        acc[2][0] += hv2 * wv0; acc[2][1] += hv2 * wv1; acc[2][2] += hv2 * wv2; acc[2][3] += hv2 * wv3;
        acc[3][0] += hv3 * wv0; acc[3][1] += hv3 * wv1; acc[3][2] += hv3 * wv2; acc[3][3] += hv3 * wv3;
    }

    float* outp = &g_dotp[(size_t)dc * (B_SZ * H_DIM)];
#pragma unroll
    for (int j = 0; j < 4; ++j) {
        int b = bl + j;
#pragma unroll
        for (int i = 0; i < 4; ++i) {
            int h = h0 + hl + 16 * i;
            outp[b * H_DIM + h] = acc[j][i];
        }
    }
}

// ---------------------------------------------------------------------------
// K2 (fused): one block per b, 512 threads.
//   phase 1: reduce g_dotp -> tanh -> dot(vp_w) -> p, center
//   phase 2: scores[w] = dot(hidden[b], enc[s,b,:])   (DRAM pass)
//   phase 3: softmax over w  x  gaussian(p)           (smem)
//   phase 4: context[h] = sum_w attn[w]*enc[s,b,h]    (L2-hot pass)
// ---------------------------------------------------------------------------
__global__ __launch_bounds__(512)
void k_attn_fused(const float* __restrict__ hidden,
                  const float* __restrict__ enc,
                  const float* __restrict__ Wp_b,
                  const float* __restrict__ vp_w,
                  const float* __restrict__ vp_b,
                  float* __restrict__ d_out) {
    const int b    = blockIdx.x;
    const int tid  = threadIdx.x;
    const int lane = tid & 31;
    const int warp = tid >> 5;

    __shared__ __align__(16) float sh_hid[H_DIM];
    __shared__ float s_scores[W_WIN];
    __shared__ float s_attn[W_WIN];
    __shared__ float red[256];
    __shared__ float warp_red[16];
    __shared__ float s_p;
    __shared__ int   s_c;

    // stage hidden row (used by phase 2)
    for (int i = tid; i < H_DIM; i += 512) sh_hid[i] = hidden[b * H_DIM + i];

    // ---- phase 1: p and center ----
    float local = 0.f;
    for (int h = tid; h < H_DIM; h += 512) {
        float s = Wp_b[h];
#pragma unroll
        for (int dc = 0; dc < NDC; ++dc)
            s += g_dotp[dc * (B_SZ * H_DIM) + b * H_DIM + h];
        local += vp_w[h] * tanhf(s);
    }
#pragma unroll
    for (int off = 16; off > 0; off >>= 1)
        local += __shfl_down_sync(0xffffffffu, local, off);
    if (lane == 0) warp_red[warp] = local;
    __syncthreads();
    if (warp == 0) {
        float v = (lane < 16) ? warp_red[lane] : 0.f;
#pragma unroll
        for (int off = 8; off > 0; off >>= 1)
            v += __shfl_down_sync(0xffffffffu, v, off);
        if (lane == 0) {
            float tot = v + vp_b[0];
            float p = (float)S_LEN / (1.f + expf(-tot));
            s_p = p;
            s_c = (int)rintf(p);   // round-half-even == jnp.round
        }
    }
    __syncthreads();
    const int   c = s_c;
    const float p = s_p;

    // ---- phase 2: scores (one warp per window position) ----
    for (int w = warp; w < W_WIN; w += 16) {
        const int s = c + w - D_HALF;
        float score = 0.f;
        if (s >= 0 && s < S_LEN) {
            const float4* e4 = reinterpret_cast<const float4*>(enc + ((size_t)s * B_SZ + b) * H_DIM);
            const float4* h4 = reinterpret_cast<const float4*>(sh_hid);
            float a0 = 0.f, a1 = 0.f, a2 = 0.f, a3 = 0.f;
#pragma unroll
            for (int k = 0; k < 8; ++k) {
                float4 e  = e4[k * 32 + lane];
                float4 hh = h4[k * 32 + lane];
                a0 += e.x * hh.x; a1 += e.y * hh.y;
                a2 += e.z * hh.z; a3 += e.w * hh.w;
            }
            float v = (a0 + a1) + (a2 + a3);
#pragma unroll
            for (int off = 16; off > 0; off >>= 1)
                v += __shfl_down_sync(0xffffffffu, v, off);
            score = v;
        }
        if (lane == 0) s_scores[w] = score;
    }
    __syncthreads();

    // ---- phase 3: softmax x gaussian ----
    float sc = (tid < W_WIN) ? s_scores[tid] : -1e30f;
    if (tid < 256) red[tid] = sc;
    __syncthreads();
    for (int s2 = 128; s2 > 0; s2 >>= 1) {
        if (tid < s2) red[tid] = fmaxf(red[tid], red[tid + s2]);
        __syncthreads();
    }
    float mx = red[0];
    __syncthreads();
    float e = (tid < W_WIN) ? expf(sc - mx) : 0.f;
    if (tid < 256) red[tid] = e;
    __syncthreads();
    for (int s2 = 128; s2 > 0; s2 >>= 1) {
        if (tid < s2) red[tid] += red[tid + s2];
        __syncthreads();
    }
    float denom = red[0];
    if (tid < W_WIN) {
        float pos  = (float)(c + tid - D_HALF);
        float diff = pos - p;
        float val = (e / denom) * expf(-diff * diff * (1.f / 2048.f)); // stddev=D/2=32
        s_attn[tid] = val;
        d_out[b * W_WIN + tid] = val;
    }
    __syncthreads();

    // ---- phase 4: context (L2-hot second pass over the window) ----
    const int wlo = max(0, D_HALF - c);
    const int whi = min(W_WIN, S_LEN + D_HALF - c);
    const int h   = tid * 2;

    const float* base = enc + (size_t)b * H_DIM + h;
    float ax = 0.f, ay = 0.f;
#pragma unroll 4
    for (int w = wlo; w < whi; ++w) {
        float a = s_attn[w];
        const float2 ev = *reinterpret_cast<const float2*>(
            base + (size_t)(c + w - D_HALF) * (B_SZ * H_DIM));
        ax += a * ev.x;
        ay += a * ev.y;
    }
    float2 outv = make_float2(ax, ay);
    *reinterpret_cast<float2*>(d_out + B_SZ * W_WIN + b * H_DIM + h) = outv;
}

// ---------------------------------------------------------------------------
extern "C" void kernel_launch(void* const* d_in, const int* in_sizes, int n_in,
                              void* d_out, int out_size) {
    // metadata order: t, hidden, encoder_outputs, Wp_w, Wp_b, vp_w, vp_b
    const float* hidden = (const float*)d_in[1];
    const float* enc    = (const float*)d_in[2];
    const float* Wp_w   = (const float*)d_in[3];
    const float* Wp_b   = (const float*)d_in[4];
    const float* vp_w   = (const float*)d_in[5];
    const float* vp_b   = (const float*)d_in[6];
    float* out = (float*)d_out;

    k_gemm_partial<<<dim3(16, 16), 256>>>(hidden, Wp_w);
    k_attn_fused<<<64, 512>>>(hidden, enc, Wp_b, vp_w, vp_b, out);
}

// round 3
// speedup vs baseline: 1.3740x; 1.3635x over previous
#include <cuda_runtime.h>
#include <math.h>

// Problem constants (fixed shapes)
#define S_LEN 2048
#define B_SZ  64
#define H_DIM 1024
#define D_HALF 64
#define W_WIN 129          // 2*D+1
#define DCH   64           // d-chunk for GEMM partial
#define NDC   (H_DIM / DCH)  // 16

// Scratch (allocation-free)
__device__ float g_dotp[NDC * B_SZ * H_DIM];   // [dc][b][h]  4 MB

// ---------------------------------------------------------------------------
// K1: partial GEMM  dotp[dc][b][h] = sum_{d in chunk dc} hidden[b][d]*Wp_w[h][d]
// fp32 on purpose: p feeds round() -> window center; precision is structural.
// ---------------------------------------------------------------------------
__global__ __launch_bounds__(256, 2)
void k_gemm_partial(const float* __restrict__ hidden,
                    const float* __restrict__ Wp_w) {
    const int h0 = blockIdx.x * 64;
    const int dc = blockIdx.y;
    const int d0 = dc * DCH;

    __shared__ float sh_h[64][65];   // [b][d] padded
    __shared__ float sh_w[DCH][65];  // [d][h] padded (transposed)

    const int tid  = threadIdx.x;
    const int lane = tid & 31;
    const int warp = tid >> 5;

    for (int idx = tid; idx < 64 * 16; idx += 256) {
        int b  = idx >> 4;
        int dq = (idx & 15) << 2;
        float4 v = *reinterpret_cast<const float4*>(&hidden[b * H_DIM + d0 + dq]);
        sh_h[b][dq + 0] = v.x; sh_h[b][dq + 1] = v.y;
        sh_h[b][dq + 2] = v.z; sh_h[b][dq + 3] = v.w;
    }
    for (int idx = tid; idx < 64 * 16; idx += 256) {
        int h  = idx >> 4;
        int dq = (idx & 15) << 2;
        float4 v = *reinterpret_cast<const float4*>(&Wp_w[(size_t)(h0 + h) * H_DIM + d0 + dq]);
        sh_w[dq + 0][h] = v.x; sh_w[dq + 1][h] = v.y;
        sh_w[dq + 2][h] = v.z; sh_w[dq + 3][h] = v.w;
    }
    __syncthreads();

    const int hl = lane & 15;
    const int bl = ((lane >> 4) << 2) + (warp << 3);

    float acc[4][4] = {};
#pragma unroll 16
    for (int d = 0; d < DCH; ++d) {
        float wv0 = sh_w[d][hl];
        float wv1 = sh_w[d][hl + 16];
        float wv2 = sh_w[d][hl + 32];
        float wv3 = sh_w[d][hl + 48];
        float hv0 = sh_h[bl + 0][d];
        float hv1 = sh_h[bl + 1][d];
        float hv2 = sh_h[bl + 2][d];
        float hv3 = sh_h[bl + 3][d];
        acc[0][0] += hv0 * wv0; acc[0][1] += hv0 * wv1; acc[0][2] += hv0 * wv2; acc[0][3] += hv0 * wv3;
        acc[1][0] += hv1 * wv0; acc[1][1] += hv1 * wv1; acc[1][2] += hv1 * wv2; acc[1][3] += hv1 * wv3;
        acc[2][0] += hv2 * wv0; acc[2][1] += hv2 * wv1; acc[2][2] += hv2 * wv2; acc[2][3] += hv2 * wv3;
        acc[3][0] += hv3 * wv0; acc[3][1] += hv3 * wv1; acc[3][2] += hv3 * wv2; acc[3][3] += hv3 * wv3;
    }

    float* outp = &g_dotp[(size_t)dc * (B_SZ * H_DIM)];
#pragma unroll
    for (int j = 0; j < 4; ++j) {
        int b = bl + j;
#pragma unroll
        for (int i = 0; i < 4; ++i) {
            int h = h0 + hl + 16 * i;
            outp[b * H_DIM + h] = acc[j][i];
        }
    }
}

// ---------------------------------------------------------------------------
// K2 (fused): one block per b, 512 threads, high-MLP memory phases.
// ---------------------------------------------------------------------------
__global__ __launch_bounds__(512, 1)
void k_attn_fused(const float* __restrict__ hidden,
                  const float* __restrict__ enc,
                  const float* __restrict__ Wp_b,
                  const float* __restrict__ vp_w,
                  const float* __restrict__ vp_b,
                  float* __restrict__ d_out) {
    const int b    = blockIdx.x;
    const int tid  = threadIdx.x;
    const int lane = tid & 31;
    const int warp = tid >> 5;

    __shared__ __align__(16) float sh_hid[H_DIM];
    __shared__ float  s_scores[W_WIN];
    __shared__ float  s_attn[W_WIN];
    __shared__ float  red[256];
    __shared__ float  warp_red[16];
    __shared__ float4 s_ctx[256];
    __shared__ float  s_p;
    __shared__ int    s_c;

    // stage hidden row
    for (int i = tid; i < H_DIM; i += 512) sh_hid[i] = hidden[b * H_DIM + i];

    // ---- phase 1: p and center ----
    float local = 0.f;
    for (int h = tid; h < H_DIM; h += 512) {
        float pa[NDC];
#pragma unroll
        for (int dc = 0; dc < NDC; ++dc)
            pa[dc] = g_dotp[dc * (B_SZ * H_DIM) + b * H_DIM + h];
        float s = Wp_b[h];
#pragma unroll
        for (int dc = 0; dc < NDC; ++dc) s += pa[dc];
        local += vp_w[h] * tanhf(s);
    }
#pragma unroll
    for (int off = 16; off > 0; off >>= 1)
        local += __shfl_down_sync(0xffffffffu, local, off);
    if (lane == 0) warp_red[warp] = local;
    __syncthreads();
    if (warp == 0) {
        float v = (lane < 16) ? warp_red[lane] : 0.f;
#pragma unroll
        for (int off = 8; off > 0; off >>= 1)
            v += __shfl_down_sync(0xffffffffu, v, off);
        if (lane == 0) {
            float tot = v + vp_b[0];
            float p = (float)S_LEN / (1.f + expf(-tot));
            s_p = p;
            s_c = (int)rintf(p);   // round-half-even == jnp.round
        }
    }
    __syncthreads();
    const int   c = s_c;
    const float p = s_p;

    // ---- phase 2: scores, one warp per window position, MLP=8 ----
    const float4* h4 = reinterpret_cast<const float4*>(sh_hid);
    for (int w = warp; w < W_WIN; w += 16) {
        const int s = c + w - D_HALF;
        float score = 0.f;
        if (s >= 0 && s < S_LEN) {
            const float4* e4 = reinterpret_cast<const float4*>(
                enc + ((size_t)s * B_SZ + b) * H_DIM);
            float4 e[8];
#pragma unroll
            for (int k = 0; k < 8; ++k) e[k] = e4[k * 32 + lane];   // batched LDG.128
            float a0 = 0.f, a1 = 0.f, a2 = 0.f, a3 = 0.f;
#pragma unroll
            for (int k = 0; k < 8; ++k) {
                float4 hh = h4[k * 32 + lane];
                a0 += e[k].x * hh.x; a1 += e[k].y * hh.y;
                a2 += e[k].z * hh.z; a3 += e[k].w * hh.w;
            }
            float v = (a0 + a1) + (a2 + a3);
#pragma unroll
            for (int off = 16; off > 0; off >>= 1)
                v += __shfl_down_sync(0xffffffffu, v, off);
            score = v;
        }
        if (lane == 0) s_scores[w] = score;
    }
    __syncthreads();

    // ---- phase 3: softmax x gaussian ----
    float sc = (tid < W_WIN) ? s_scores[tid] : -1e30f;
    if (tid < 256) red[tid] = sc;
    __syncthreads();
    for (int s2 = 128; s2 > 0; s2 >>= 1) {
        if (tid < s2) red[tid] = fmaxf(red[tid], red[tid + s2]);
        __syncthreads();
    }
    float mx = red[0];
    __syncthreads();
    float e = (tid < W_WIN) ? expf(sc - mx) : 0.f;
    if (tid < 256) red[tid] = e;
    __syncthreads();
    for (int s2 = 128; s2 > 0; s2 >>= 1) {
        if (tid < s2) red[tid] += red[tid + s2];
        __syncthreads();
    }
    float denom = red[0];
    if (tid < W_WIN) {
        float pos  = (float)(c + tid - D_HALF);
        float diff = pos - p;
        float val = (e / denom) * expf(-diff * diff * (1.f / 2048.f)); // stddev=D/2=32
        s_attn[tid] = val;
        d_out[b * W_WIN + tid] = val;
    }
    __syncthreads();

    // ---- phase 4: context, 2 w-segments x 256 h-threads, MLP=8 ----
    const int wlo = max(0, D_HALF - c);
    const int whi = min(W_WIN, S_LEN + D_HALF - c);
    const int seg  = tid >> 8;       // 0 or 1
    const int hidx = tid & 255;      // float4 index in h

    const float4* base = reinterpret_cast<const float4*>(enc + (size_t)b * H_DIM) + hidx;
    const size_t rowstride4 = (size_t)(B_SZ * H_DIM) / 4;

    float4 acc = make_float4(0.f, 0.f, 0.f, 0.f);
    int w = wlo + seg;
    // 8-deep staged main loop (each iteration advances 16 w's at step 2)
    for (; w + 14 < whi; w += 16) {
        float4 ev[8];
        float  av[8];
#pragma unroll
        for (int j = 0; j < 8; ++j) {
            int ww = w + 2 * j;
            ev[j] = base[(size_t)(c + ww - D_HALF) * rowstride4];   // batched LDG.128
            av[j] = s_attn[ww];
        }
#pragma unroll
        for (int j = 0; j < 8; ++j) {
            acc.x += av[j] * ev[j].x; acc.y += av[j] * ev[j].y;
            acc.z += av[j] * ev[j].z; acc.w += av[j] * ev[j].w;
        }
    }
    for (; w < whi; w += 2) {
        float4 ev = base[(size_t)(c + w - D_HALF) * rowstride4];
        float  a  = s_attn[w];
        acc.x += a * ev.x; acc.y += a * ev.y;
        acc.z += a * ev.z; acc.w += a * ev.w;
    }

    if (seg == 1) s_ctx[hidx] = acc;
    __syncthreads();
    if (seg == 0) {
        float4 o = s_ctx[hidx];
        o.x += acc.x; o.y += acc.y; o.z += acc.z; o.w += acc.w;
        reinterpret_cast<float4*>(d_out + B_SZ * W_WIN + b * H_DIM)[hidx] = o;
    }
}

// ---------------------------------------------------------------------------
extern "C" void kernel_launch(void* const* d_in, const int* in_sizes, int n_in,
                              void* d_out, int out_size) {
    // metadata order: t, hidden, encoder_outputs, Wp_w, Wp_b, vp_w, vp_b
    const float* hidden = (const float*)d_in[1];
    const float* enc    = (const float*)d_in[2];
    const float* Wp_w   = (const float*)d_in[3];
    const float* Wp_b   = (const float*)d_in[4];
    const float* vp_w   = (const float*)d_in[5];
    const float* vp_b   = (const float*)d_in[6];
    float* out = (float*)d_out;

    k_gemm_partial<<<dim3(16, 16), 256>>>(hidden, Wp_w);
    k_attn_fused<<<64, 512>>>(hidden, enc, Wp_b, vp_w, vp_b, out);
}